// round 1
// baseline (speedup 1.0000x reference)
#include <cuda_runtime.h>
#include <cuda_bf16.h>
#include <math_constants.h>
#include <cstdint>

#define N_ROWS 2048
#define DIM    1024
#define VOC    32000
#define KNN    32

// ---------------- scratch (static device globals: allocation-free) ----------
__device__ __nv_bfloat16 g_featb[(size_t)N_ROWS * 2048]; // [N, 2D] bf16
__device__ __nv_bfloat16 g_wb[(size_t)DIM * 2048];       // mw_w1 bf16
__device__ float g_mhid[(size_t)N_ROWS * DIM];           // relu(feat@w1^T+b1)
__device__ float g_knnw[N_ROWS * KNN];                   // softmax(-d/bw)
__device__ float g_mixing[N_ROWS];                       // sigmoid(...)

// ---------------- k0: convert mw_w1 to bf16 ---------------------------------
__global__ void k0_convert_w(const float* __restrict__ w1) {
    int idx = blockIdx.x * blockDim.x + threadIdx.x;     // exactly DIM*2048
    g_wb[idx] = __float2bfloat16(w1[idx]);
}

// ---------------- k1: ctx mean + feat(bf16) + bandwidth + knn softmax -------
__global__ void k1_ctx(const float* __restrict__ hidden,
                       const float* __restrict__ sh,
                       const float* __restrict__ dist,
                       const float* __restrict__ bw_w,
                       const float* __restrict__ bw_b) {
    int n = blockIdx.x;
    int tid = threadIdx.x;                               // 256 threads
    const float* shrow = sh + (size_t)n * KNN * DIM;
    const float* hrow  = hidden + (size_t)n * DIM;
    float bwacc = 0.f;
    for (int d = tid; d < DIM; d += 256) {
        float acc = 0.f;
        #pragma unroll
        for (int k = 0; k < KNN; k++) acc += shrow[k * DIM + d];
        float ctx = acc * (1.f / 32.f);
        float h = hrow[d];
        g_featb[(size_t)n * 2048 + d]        = __float2bfloat16(h);
        g_featb[(size_t)n * 2048 + DIM + d]  = __float2bfloat16(ctx);
        bwacc = fmaf(h,   bw_w[d],       bwacc);
        bwacc = fmaf(ctx, bw_w[DIM + d], bwacc);
    }
    __shared__ float red[8];
    #pragma unroll
    for (int o = 16; o > 0; o >>= 1) bwacc += __shfl_xor_sync(0xffffffffu, bwacc, o);
    if ((tid & 31) == 0) red[tid >> 5] = bwacc;
    __syncthreads();
    __shared__ float s_bw;
    if (tid == 0) {
        float t = 0.f;
        #pragma unroll
        for (int i = 0; i < 8; i++) t += red[i];
        s_bw = expf(t + bw_b[0]);
    }
    __syncthreads();
    if (tid < 32) {
        float bw = s_bw;
        float t = -dist[n * KNN + tid] / bw;
        float m = t;
        #pragma unroll
        for (int o = 16; o > 0; o >>= 1) m = fmaxf(m, __shfl_xor_sync(0xffffffffu, m, o));
        float e = __expf(t - m);
        float ssum = e;
        #pragma unroll
        for (int o = 16; o > 0; o >>= 1) ssum += __shfl_xor_sync(0xffffffffu, ssum, o);
        g_knnw[n * KNN + tid] = e / ssum;
    }
}

// ---------------- k2: bf16 MMA GEMM  mhid = relu(feat @ w1^T + b1) ----------
// M=2048, N=1024, K=2048. BM=BN=128, BK=32, 8 warps (4m x 2n), warp tile 32x64.
#define BM 128
#define BN 128
#define BK 32
#define SSTR 40   // smem row stride (bf16): conflict-free, 16B-aligned rows

__device__ __forceinline__ void mma16816(float c[4], const uint32_t a[4], const uint32_t b[2]) {
    asm volatile(
        "mma.sync.aligned.m16n8k16.row.col.f32.bf16.bf16.f32 "
        "{%0,%1,%2,%3}, {%4,%5,%6,%7}, {%8,%9}, {%0,%1,%2,%3};\n"
        : "+f"(c[0]), "+f"(c[1]), "+f"(c[2]), "+f"(c[3])
        : "r"(a[0]), "r"(a[1]), "r"(a[2]), "r"(a[3]), "r"(b[0]), "r"(b[1]));
}

__global__ __launch_bounds__(256) void k2_gemm(const float* __restrict__ b1) {
    __shared__ __nv_bfloat16 As[BM * SSTR];
    __shared__ __nv_bfloat16 Bs[BN * SSTR];
    int tid = threadIdx.x;
    int lane = tid & 31, warp = tid >> 5;
    int wm = warp >> 1, wn = warp & 1;
    int g = lane >> 2, q = lane & 3;
    int bmrow = blockIdx.y * BM;
    int bncol = blockIdx.x * BN;

    float acc[2][8][4];
    #pragma unroll
    for (int i = 0; i < 2; i++)
        #pragma unroll
        for (int j = 0; j < 8; j++)
            #pragma unroll
            for (int c = 0; c < 4; c++) acc[i][j][c] = 0.f;

    int r0 = tid >> 2;               // 0..63
    int cs0 = (tid & 3) * 8;         // 0,8,16,24 (bf16 elems)
    const __nv_bfloat16* Ag  = g_featb + (size_t)(bmrow + r0) * 2048 + cs0;
    const __nv_bfloat16* Ag2 = Ag + (size_t)64 * 2048;
    const __nv_bfloat16* Bg  = g_wb   + (size_t)(bncol + r0) * 2048 + cs0;
    const __nv_bfloat16* Bg2 = Bg + (size_t)64 * 2048;

    uint4 pa0 = *(const uint4*)(Ag);
    uint4 pa1 = *(const uint4*)(Ag2);
    uint4 pb0 = *(const uint4*)(Bg);
    uint4 pb1 = *(const uint4*)(Bg2);

    const int KT = 2048 / BK;        // 64
    for (int kt = 0; kt < KT; kt++) {
        *(uint4*)&As[r0 * SSTR + cs0]        = pa0;
        *(uint4*)&As[(r0 + 64) * SSTR + cs0] = pa1;
        *(uint4*)&Bs[r0 * SSTR + cs0]        = pb0;
        *(uint4*)&Bs[(r0 + 64) * SSTR + cs0] = pb1;
        __syncthreads();
        if (kt + 1 < KT) {
            int kb = (kt + 1) * BK;
            pa0 = *(const uint4*)(Ag + kb);
            pa1 = *(const uint4*)(Ag2 + kb);
            pb0 = *(const uint4*)(Bg + kb);
            pb1 = *(const uint4*)(Bg2 + kb);
        }
        #pragma unroll
        for (int ks = 0; ks < BK; ks += 16) {
            uint32_t a[2][4], b[8][2];
            #pragma unroll
            for (int mt = 0; mt < 2; mt++) {
                int rr = (wm * 32 + mt * 16 + g) * SSTR + ks + q * 2;
                a[mt][0] = *(const uint32_t*)&As[rr];
                a[mt][1] = *(const uint32_t*)&As[rr + 8 * SSTR];
                a[mt][2] = *(const uint32_t*)&As[rr + 8];
                a[mt][3] = *(const uint32_t*)&As[rr + 8 * SSTR + 8];
            }
            #pragma unroll
            for (int nt = 0; nt < 8; nt++) {
                int rr = (wn * 64 + nt * 8 + g) * SSTR + ks + q * 2;
                b[nt][0] = *(const uint32_t*)&Bs[rr];
                b[nt][1] = *(const uint32_t*)&Bs[rr + 8];
            }
            #pragma unroll
            for (int mt = 0; mt < 2; mt++)
                #pragma unroll
                for (int nt = 0; nt < 8; nt++)
                    mma16816(acc[mt][nt], a[mt], b[nt]);
        }
        __syncthreads();
    }

    #pragma unroll
    for (int mt = 0; mt < 2; mt++) {
        int row = bmrow + wm * 32 + mt * 16 + g;
        #pragma unroll
        for (int nt = 0; nt < 8; nt++) {
            int col = bncol + wn * 64 + nt * 8 + q * 2;
            float bb0 = b1[col], bb1 = b1[col + 1];
            g_mhid[(size_t)row * DIM + col]           = fmaxf(acc[mt][nt][0] + bb0, 0.f);
            g_mhid[(size_t)row * DIM + col + 1]       = fmaxf(acc[mt][nt][1] + bb1, 0.f);
            g_mhid[(size_t)(row + 8) * DIM + col]     = fmaxf(acc[mt][nt][2] + bb0, 0.f);
            g_mhid[(size_t)(row + 8) * DIM + col + 1] = fmaxf(acc[mt][nt][3] + bb1, 0.f);
        }
    }
}

// ---------------- k3: mixing = sigmoid(mhid @ w2 + b2) ----------------------
__global__ void k3_mix(const float* __restrict__ w2, const float* __restrict__ b2) {
    int warp = threadIdx.x >> 5, lane = threadIdx.x & 31;
    int n = blockIdx.x * 8 + warp;
    const float* row = g_mhid + (size_t)n * DIM;
    float acc = 0.f;
    for (int j = lane; j < DIM; j += 32) acc = fmaf(row[j], w2[j], acc);
    #pragma unroll
    for (int o = 16; o > 0; o >>= 1) acc += __shfl_xor_sync(0xffffffffu, acc, o);
    if (lane == 0) g_mixing[n] = 1.f / (1.f + __expf(-(acc + b2[0])));
}

// ---------------- k4: softmax(logits), sparse scatter, log ------------------
__global__ __launch_bounds__(1024) void k4_out(const float* __restrict__ logits,
                                               const int* __restrict__ tok,
                                               float* __restrict__ out) {
    extern __shared__ float sm[];          // VOC floats = 128000 B
    __shared__ float redm[32], reds[32];
    int n = blockIdx.x;
    int tid = threadIdx.x;
    int lane = tid & 31, warp = tid >> 5;
    const float* lrow = logits + (size_t)n * VOC;

    float m = -CUDART_INF_F, s = 0.f;
    for (int i = tid; i < VOC; i += 1024) {
        float x = lrow[i];
        sm[i] = x;
        float mn = fmaxf(m, x);
        s = s * __expf(m - mn) + __expf(x - mn);
        m = mn;
    }
    #pragma unroll
    for (int o = 16; o > 0; o >>= 1) {
        float m2 = __shfl_xor_sync(0xffffffffu, m, o);
        float s2 = __shfl_xor_sync(0xffffffffu, s, o);
        float mn = fmaxf(m, m2);
        s = s * __expf(m - mn) + s2 * __expf(m2 - mn);
        m = mn;
    }
    if (lane == 0) { redm[warp] = m; reds[warp] = s; }
    __syncthreads();
    if (warp == 0) {
        m = redm[lane]; s = reds[lane];
        #pragma unroll
        for (int o = 16; o > 0; o >>= 1) {
            float m2 = __shfl_xor_sync(0xffffffffu, m, o);
            float s2 = __shfl_xor_sync(0xffffffffu, s, o);
            float mn = fmaxf(m, m2);
            s = s * __expf(m - mn) + s2 * __expf(m2 - mn);
            m = mn;
        }
        if (lane == 0) { redm[0] = m; reds[0] = s; }
    }
    __syncthreads();
    float M = redm[0];
    float mix = g_mixing[n];
    float coef = (1.f - mix) / reds[0];
    for (int i = tid; i < VOC; i += 1024)
        sm[i] = coef * __expf(sm[i] - M);
    __syncthreads();
    if (tid < KNN) {
        float w = g_knnw[n * KNN + tid] * mix;
        atomicAdd(&sm[tok[n * KNN + tid]], w);   // duplicates accumulate, matching .at[].add
    }
    __syncthreads();
    float* orow = out + (size_t)n * VOC;
    for (int i = tid; i < VOC; i += 1024)
        orow[i] = __logf(sm[i] + 1e-10f);
}

// ---------------- launch -----------------------------------------------------
extern "C" void kernel_launch(void* const* d_in, const int* in_sizes, int n_in,
                              void* d_out, int out_size) {
    const float* hidden = (const float*)d_in[0];
    const float* logits = (const float*)d_in[1];
    const float* dist   = (const float*)d_in[2];
    const int*   tok    = (const int*)d_in[3];
    const float* sh     = (const float*)d_in[4];
    const float* bw_w   = (const float*)d_in[5];
    const float* bw_b   = (const float*)d_in[6];
    const float* mw_w1  = (const float*)d_in[7];
    const float* mw_b1  = (const float*)d_in[8];
    const float* mw_w2  = (const float*)d_in[9];
    const float* mw_b2  = (const float*)d_in[10];
    float* out = (float*)d_out;

    cudaFuncSetAttribute(k4_out, cudaFuncAttributeMaxDynamicSharedMemorySize,
                         VOC * (int)sizeof(float));

    k0_convert_w<<<2048, 1024>>>(mw_w1);
    k1_ctx<<<N_ROWS, 256>>>(hidden, sh, dist, bw_w, bw_b);
    dim3 g2(DIM / BN, N_ROWS / BM);   // (8, 16)
    k2_gemm<<<g2, 256>>>(mw_b1);
    k3_mix<<<N_ROWS / 8, 256>>>(mw_w2, mw_b2);
    k4_out<<<N_ROWS, 1024, VOC * sizeof(float)>>>(logits, tok, out);
}

// round 3
// speedup vs baseline: 1.1291x; 1.1291x over previous
#include <cuda_runtime.h>
#include <cuda_bf16.h>
#include <math_constants.h>
#include <cstdint>

#define N_ROWS 2048
#define DIM    1024
#define VOC    32000
#define KNN    32

// ---------------- scratch (static device globals: allocation-free) ----------
__device__ __nv_bfloat16 g_featb[(size_t)N_ROWS * 2048]; // [N, 2D] bf16
__device__ __nv_bfloat16 g_wb[(size_t)DIM * 2048];       // mw_w1 bf16
__device__ float g_knnw[N_ROWS * KNN];                   // softmax(-d/bw)
__device__ float g_mixp[N_ROWS];                         // partial mhid.w2 dots

// ---------------- k0: convert mw_w1 to bf16 + zero mixing partials ----------
__global__ void k0_convert_w(const float* __restrict__ w1) {
    int idx = blockIdx.x * blockDim.x + threadIdx.x;     // exactly DIM*2048
    g_wb[idx] = __float2bfloat16(w1[idx]);
    if (idx < N_ROWS) g_mixp[idx] = 0.f;
}

// ---------------- k1: ctx mean + feat(bf16) + bandwidth + knn softmax -------
__global__ __launch_bounds__(256) void k1_ctx(const float* __restrict__ hidden,
                       const float* __restrict__ sh,
                       const float* __restrict__ dist,
                       const float* __restrict__ bw_w,
                       const float* __restrict__ bw_b) {
    int n = blockIdx.x;
    int tid = threadIdx.x;                               // 256 threads
    int d = tid * 4;                                     // each thread: 4 dims
    const float* shrow = sh + (size_t)n * KNN * DIM;
    const float* hrow  = hidden + (size_t)n * DIM;

    float4 acc = make_float4(0.f, 0.f, 0.f, 0.f);
    #pragma unroll
    for (int k = 0; k < KNN; k++) {
        float4 v = *(const float4*)(shrow + k * DIM + d);
        acc.x += v.x; acc.y += v.y; acc.z += v.z; acc.w += v.w;
    }
    const float inv = 1.f / 32.f;
    float4 ctx = make_float4(acc.x * inv, acc.y * inv, acc.z * inv, acc.w * inv);
    float4 h = *(const float4*)(hrow + d);

    // store bf16 feat: [h | ctx]
    __nv_bfloat162* fb = (__nv_bfloat162*)&g_featb[(size_t)n * 2048 + d];
    fb[0] = __nv_bfloat162(__float2bfloat16(h.x), __float2bfloat16(h.y));
    fb[1] = __nv_bfloat162(__float2bfloat16(h.z), __float2bfloat16(h.w));
    __nv_bfloat162* fb2 = (__nv_bfloat162*)&g_featb[(size_t)n * 2048 + DIM + d];
    fb2[0] = __nv_bfloat162(__float2bfloat16(ctx.x), __float2bfloat16(ctx.y));
    fb2[1] = __nv_bfloat162(__float2bfloat16(ctx.z), __float2bfloat16(ctx.w));

    float4 w0 = *(const float4*)(bw_w + d);
    float4 w1 = *(const float4*)(bw_w + DIM + d);
    float bwacc = h.x * w0.x + h.y * w0.y + h.z * w0.z + h.w * w0.w
                + ctx.x * w1.x + ctx.y * w1.y + ctx.z * w1.z + ctx.w * w1.w;

    __shared__ float red[8];
    #pragma unroll
    for (int o = 16; o > 0; o >>= 1) bwacc += __shfl_xor_sync(0xffffffffu, bwacc, o);
    if ((tid & 31) == 0) red[tid >> 5] = bwacc;
    __syncthreads();
    __shared__ float s_bw;
    if (tid == 0) {
        float t = 0.f;
        #pragma unroll
        for (int i = 0; i < 8; i++) t += red[i];
        s_bw = expf(t + bw_b[0]);
    }
    __syncthreads();
    if (tid < 32) {
        float bw = s_bw;
        float t = -dist[n * KNN + tid] / bw;
        float m = t;
        #pragma unroll
        for (int o = 16; o > 0; o >>= 1) m = fmaxf(m, __shfl_xor_sync(0xffffffffu, m, o));
        float e = __expf(t - m);
        float ssum = e;
        #pragma unroll
        for (int o = 16; o > 0; o >>= 1) ssum += __shfl_xor_sync(0xffffffffu, ssum, o);
        g_knnw[n * KNN + tid] = e / ssum;
    }
}

// ---------------- k2: bf16 MMA GEMM + fused mixing partial dot --------------
// mhid = relu(feat @ w1^T + b1) consumed in-register: g_mixp[row] += mhid.w2
#define BM 128
#define BN 128
#define BK 32
#define SSTR 40   // smem row stride (bf16): conflict-free, 16B-aligned rows

__device__ __forceinline__ void mma16816(float c[4], const uint32_t a[4], const uint32_t b[2]) {
    asm volatile(
        "mma.sync.aligned.m16n8k16.row.col.f32.bf16.bf16.f32 "
        "{%0,%1,%2,%3}, {%4,%5,%6,%7}, {%8,%9}, {%0,%1,%2,%3};\n"
        : "+f"(c[0]), "+f"(c[1]), "+f"(c[2]), "+f"(c[3])
        : "r"(a[0]), "r"(a[1]), "r"(a[2]), "r"(a[3]), "r"(b[0]), "r"(b[1]));
}

__global__ __launch_bounds__(256) void k2_gemm(const float* __restrict__ b1,
                                               const float* __restrict__ w2) {
    __shared__ __nv_bfloat16 As[BM * SSTR];
    __shared__ __nv_bfloat16 Bs[BN * SSTR];
    int tid = threadIdx.x;
    int lane = tid & 31, warp = tid >> 5;
    int wm = warp >> 1, wn = warp & 1;
    int g = lane >> 2, q = lane & 3;
    int bmrow = blockIdx.y * BM;
    int bncol = blockIdx.x * BN;

    float acc[2][8][4];
    #pragma unroll
    for (int i = 0; i < 2; i++)
        #pragma unroll
        for (int j = 0; j < 8; j++)
            #pragma unroll
            for (int c = 0; c < 4; c++) acc[i][j][c] = 0.f;

    int r0 = tid >> 2;               // 0..63
    int cs0 = (tid & 3) * 8;         // 0,8,16,24 (bf16 elems)
    const __nv_bfloat16* Ag  = g_featb + (size_t)(bmrow + r0) * 2048 + cs0;
    const __nv_bfloat16* Ag2 = Ag + (size_t)64 * 2048;
    const __nv_bfloat16* Bg  = g_wb   + (size_t)(bncol + r0) * 2048 + cs0;
    const __nv_bfloat16* Bg2 = Bg + (size_t)64 * 2048;

    uint4 pa0 = *(const uint4*)(Ag);
    uint4 pa1 = *(const uint4*)(Ag2);
    uint4 pb0 = *(const uint4*)(Bg);
    uint4 pb1 = *(const uint4*)(Bg2);

    const int KT = 2048 / BK;        // 64
    for (int kt = 0; kt < KT; kt++) {
        *(uint4*)&As[r0 * SSTR + cs0]        = pa0;
        *(uint4*)&As[(r0 + 64) * SSTR + cs0] = pa1;
        *(uint4*)&Bs[r0 * SSTR + cs0]        = pb0;
        *(uint4*)&Bs[(r0 + 64) * SSTR + cs0] = pb1;
        __syncthreads();
        if (kt + 1 < KT) {
            int kb = (kt + 1) * BK;
            pa0 = *(const uint4*)(Ag + kb);
            pa1 = *(const uint4*)(Ag2 + kb);
            pb0 = *(const uint4*)(Bg + kb);
            pb1 = *(const uint4*)(Bg2 + kb);
        }
        #pragma unroll
        for (int ks = 0; ks < BK; ks += 16) {
            uint32_t a[2][4], b[8][2];
            #pragma unroll
            for (int mt = 0; mt < 2; mt++) {
                int rr = (wm * 32 + mt * 16 + g) * SSTR + ks + q * 2;
                a[mt][0] = *(const uint32_t*)&As[rr];
                a[mt][1] = *(const uint32_t*)&As[rr + 8 * SSTR];
                a[mt][2] = *(const uint32_t*)&As[rr + 8];
                a[mt][3] = *(const uint32_t*)&As[rr + 8 * SSTR + 8];
            }
            #pragma unroll
            for (int nt = 0; nt < 8; nt++) {
                int rr = (wn * 64 + nt * 8 + g) * SSTR + ks + q * 2;
                b[nt][0] = *(const uint32_t*)&Bs[rr];
                b[nt][1] = *(const uint32_t*)&Bs[rr + 8];
            }
            #pragma unroll
            for (int mt = 0; mt < 2; mt++)
                #pragma unroll
                for (int nt = 0; nt < 8; nt++)
                    mma16816(acc[mt][nt], a[mt], b[nt]);
        }
        __syncthreads();
    }

    // Epilogue: relu(acc + b1), dot with w2, accumulate per-row mixing partials.
    #pragma unroll
    for (int mt = 0; mt < 2; mt++) {
        int row = bmrow + wm * 32 + mt * 16 + g;
        float prow = 0.f, prow8 = 0.f;
        #pragma unroll
        for (int nt = 0; nt < 8; nt++) {
            int col = bncol + wn * 64 + nt * 8 + q * 2;
            float bb0 = b1[col], bb1 = b1[col + 1];
            float w20 = w2[col], w21 = w2[col + 1];
            float v0 = fmaxf(acc[mt][nt][0] + bb0, 0.f);
            float v1 = fmaxf(acc[mt][nt][1] + bb1, 0.f);
            float v2 = fmaxf(acc[mt][nt][2] + bb0, 0.f);
            float v3 = fmaxf(acc[mt][nt][3] + bb1, 0.f);
            prow  = fmaf(v0, w20, fmaf(v1, w21, prow));
            prow8 = fmaf(v2, w20, fmaf(v3, w21, prow8));
        }
        prow  += __shfl_xor_sync(0xffffffffu, prow, 1);
        prow  += __shfl_xor_sync(0xffffffffu, prow, 2);
        prow8 += __shfl_xor_sync(0xffffffffu, prow8, 1);
        prow8 += __shfl_xor_sync(0xffffffffu, prow8, 2);
        if (q == 0) {
            atomicAdd(&g_mixp[row], prow);
            atomicAdd(&g_mixp[row + 8], prow8);
        }
    }
}

// ---------------- k4: softmax(logits), sparse scatter, log ------------------
// pass1: vec load + max (no MUFU in dep chain); pass2: exp+sum (1 exp/elem);
// scatter in exp-domain; pass3: single log/elem with streaming store.
__global__ __launch_bounds__(1024) void k4_out(const float* __restrict__ logits,
                                               const int* __restrict__ tok,
                                               const float* __restrict__ b2,
                                               float* __restrict__ out) {
    extern __shared__ float sm[];          // VOC floats = 128000 B
    __shared__ float red[32];
    __shared__ float s_M, s_coef, s_mix;
    int n = blockIdx.x;
    int tid = threadIdx.x;
    int lane = tid & 31, warp = tid >> 5;
    const float* lrow = logits + (size_t)n * VOC;

    // pass 1: load (float4, L2-cached) + running max
    float m = -CUDART_INF_F;
    #pragma unroll 8
    for (int i = tid * 4; i < VOC; i += 4096) {
        float4 x = __ldcg((const float4*)(lrow + i));
        *(float4*)&sm[i] = x;
        m = fmaxf(m, fmaxf(fmaxf(x.x, x.y), fmaxf(x.z, x.w)));
    }
    #pragma unroll
    for (int o = 16; o > 0; o >>= 1) m = fmaxf(m, __shfl_xor_sync(0xffffffffu, m, o));
    if (lane == 0) red[warp] = m;
    __syncthreads();
    if (warp == 0) {
        m = red[lane];
        #pragma unroll
        for (int o = 16; o > 0; o >>= 1) m = fmaxf(m, __shfl_xor_sync(0xffffffffu, m, o));
        if (lane == 0) s_M = m;
    }
    __syncthreads();
    float M = s_M;

    // pass 2: e = exp(x - M) into smem, accumulate sum
    float s = 0.f;
    #pragma unroll 8
    for (int i = tid * 4; i < VOC; i += 4096) {
        float4 x = *(float4*)&sm[i];
        float4 e;
        e.x = __expf(x.x - M); e.y = __expf(x.y - M);
        e.z = __expf(x.z - M); e.w = __expf(x.w - M);
        *(float4*)&sm[i] = e;
        s += (e.x + e.y) + (e.z + e.w);
    }
    #pragma unroll
    for (int o = 16; o > 0; o >>= 1) s += __shfl_xor_sync(0xffffffffu, s, o);
    if (lane == 0) red[warp] = s;
    __syncthreads();
    if (warp == 0) {
        s = red[lane];
        #pragma unroll
        for (int o = 16; o > 0; o >>= 1) s += __shfl_xor_sync(0xffffffffu, s, o);
        if (lane == 0) {
            float mix = 1.f / (1.f + expf(-(g_mixp[n] + b2[0])));
            s_mix = mix;
            s_coef = (1.f - mix) / s;   // coef: prob = coef * e
        }
    }
    __syncthreads();
    float coef = s_coef;

    // sparse scatter in exp-domain: coef*(e + w/coef) = (1-mix)p + mix*knnw
    if (tid < KNN) {
        float w = g_knnw[n * KNN + tid] * s_mix;
        atomicAdd(&sm[tok[n * KNN + tid]], w / coef);
    }
    __syncthreads();

    // pass 3: log + streaming store
    float* orow = out + (size_t)n * VOC;
    #pragma unroll 8
    for (int i = tid * 4; i < VOC; i += 4096) {
        float4 e = *(float4*)&sm[i];
        float4 o4;
        o4.x = __logf(fmaf(e.x, coef, 1e-10f));
        o4.y = __logf(fmaf(e.y, coef, 1e-10f));
        o4.z = __logf(fmaf(e.z, coef, 1e-10f));
        o4.w = __logf(fmaf(e.w, coef, 1e-10f));
        __stcs((float4*)(orow + i), o4);
    }
}

// ---------------- launch -----------------------------------------------------
extern "C" void kernel_launch(void* const* d_in, const int* in_sizes, int n_in,
                              void* d_out, int out_size) {
    const float* hidden = (const float*)d_in[0];
    const float* logits = (const float*)d_in[1];
    const float* dist   = (const float*)d_in[2];
    const int*   tok    = (const int*)d_in[3];
    const float* sh     = (const float*)d_in[4];
    const float* bw_w   = (const float*)d_in[5];
    const float* bw_b   = (const float*)d_in[6];
    const float* mw_w1  = (const float*)d_in[7];
    const float* mw_b1  = (const float*)d_in[8];
    const float* mw_w2  = (const float*)d_in[9];
    const float* mw_b2  = (const float*)d_in[10];
    float* out = (float*)d_out;

    cudaFuncSetAttribute(k4_out, cudaFuncAttributeMaxDynamicSharedMemorySize,
                         VOC * (int)sizeof(float));

    k0_convert_w<<<2048, 1024>>>(mw_w1);
    k1_ctx<<<N_ROWS, 256>>>(hidden, sh, dist, bw_w, bw_b);
    dim3 g2(DIM / BN, N_ROWS / BM);   // (8, 16)
    k2_gemm<<<g2, 256>>>(mw_b1, mw_w2);
    k4_out<<<N_ROWS, 1024, VOC * sizeof(float)>>>(logits, tok, mw_b2, out);
}